// round 1
// baseline (speedup 1.0000x reference)
#include <cuda_runtime.h>

// ---------------- problem constants ----------------
#define NTOT 2048      // N*T
#define DIM  128       // D == E1
#define NCH  16        // split-K chunks for K=2048 reductions
#define CHK  128       // NTOT / NCH
#define JROWS 288      // 36 tiles * 8 n-chunks
#define EPSV 1e-6f

// ---------------- scratch (device globals; no allocation) ----------------
static __device__ __align__(16) float g_part1[4 * NCH * 128 * 128];
static __device__ __align__(16) float g_P1  [4 * 128 * 128];
static __device__ __align__(16) float g_M   [4 * 128 * 128];
static __device__ __align__(16) float g_Hcat[NTOT * 512];
static __device__ __align__(16) float g_Htmp[NTOT * 128];
static __device__ __align__(16) float g_Hraw[NTOT * 128];
static __device__ __align__(16) float g_H   [NTOT * 128];
static __device__ __align__(16) float g_logH[NTOT * 128];
static __device__ __align__(16) float g_jpart[JROWS * 128];
static __device__ __align__(16) float g_w   [128];
static __device__ __align__(16) float g_Y   [2 * NTOT * 128];
static __device__ __align__(16) float g_partZ[2 * NCH * 128 * 128];
static __device__ __align__(16) float g_Zw  [2 * 128 * 128];

// ---------------- shared GEMM mainloops (64x64 tile, 256 thr, TM=TN=4) ----------------
// C[M,N] = A[M,K](row-major, lda) * B[K,N](row-major, ldb); accumulate tile into acc.
__device__ __forceinline__ void gemm_nn_tile(
    const float* __restrict__ A, int lda,
    const float* __restrict__ B, int ldb,
    int K, int rowBase, int colBase, float (&acc)[4][4])
{
    __shared__ float sA[16 * 68];   // transposed A tile, padded stride
    __shared__ float sB[16 * 64];
    const int tid = threadIdx.x;
    const int tx = tid & 15, ty = tid >> 4;
    const int am = tid >> 2;          // 0..63 (row within tile)
    const int ak = (tid & 3) << 2;    // 0,4,8,12 (k within tile)
    const int bk = tid >> 4;          // 0..15
    const int bn = (tid & 15) << 2;   // 0..60

    for (int kt = 0; kt < K; kt += 16) {
        float4 a4 = *(const float4*)(A + (size_t)(rowBase + am) * lda + kt + ak);
        float4 b4 = *(const float4*)(B + (size_t)(kt + bk) * ldb + colBase + bn);
        __syncthreads();
        sA[(ak + 0) * 68 + am] = a4.x;
        sA[(ak + 1) * 68 + am] = a4.y;
        sA[(ak + 2) * 68 + am] = a4.z;
        sA[(ak + 3) * 68 + am] = a4.w;
        *(float4*)(sB + bk * 64 + bn) = b4;
        __syncthreads();
#pragma unroll
        for (int k = 0; k < 16; k++) {
            float4 av = *(const float4*)(sA + k * 68 + ty * 4);
            float4 bv = *(const float4*)(sB + k * 64 + tx * 4);
            float aa[4] = {av.x, av.y, av.z, av.w};
            float bb[4] = {bv.x, bv.y, bv.z, bv.w};
#pragma unroll
            for (int u = 0; u < 4; u++)
#pragma unroll
                for (int v = 0; v < 4; v++)
                    acc[u][v] += aa[u] * bb[v];
        }
    }
}

// C[m,n] = sum_k A[k,m]*B[k,n]; A,B both [Ktot x 128] row-major (ld = 128).
__device__ __forceinline__ void gemm_tn_tile(
    const float* __restrict__ A, const float* __restrict__ B, int ld,
    int kBeg, int kEnd, int rowBase, int colBase, float (&acc)[4][4])
{
    __shared__ float sA[16 * 64];
    __shared__ float sB[16 * 64];
    const int tid = threadIdx.x;
    const int tx = tid & 15, ty = tid >> 4;
    const int lk = tid >> 4;            // 0..15
    const int lc = (tid & 15) << 2;     // 0..60

    for (int kt = kBeg; kt < kEnd; kt += 16) {
        float4 a4 = *(const float4*)(A + (size_t)(kt + lk) * ld + rowBase + lc);
        float4 b4 = *(const float4*)(B + (size_t)(kt + lk) * ld + colBase + lc);
        __syncthreads();
        *(float4*)(sA + lk * 64 + lc) = a4;
        *(float4*)(sB + lk * 64 + lc) = b4;
        __syncthreads();
#pragma unroll
        for (int k = 0; k < 16; k++) {
            float4 av = *(const float4*)(sA + k * 64 + ty * 4);
            float4 bv = *(const float4*)(sB + k * 64 + tx * 4);
            float aa[4] = {av.x, av.y, av.z, av.w};
            float bb[4] = {bv.x, bv.y, bv.z, bv.w};
#pragma unroll
            for (int u = 0; u < 4; u++)
#pragma unroll
                for (int v = 0; v < 4; v++)
                    acc[u][v] += aa[u] * bb[v];
        }
    }
}

// ---------------- block reductions ----------------
template <int NW>
__device__ __forceinline__ float block_sum(float v) {
    __shared__ float sred[8];
    __syncthreads();
#pragma unroll
    for (int o = 16; o; o >>= 1) v += __shfl_xor_sync(0xffffffffu, v, o);
    if ((threadIdx.x & 31) == 0) sred[threadIdx.x >> 5] = v;
    __syncthreads();
    float t = 0.f;
#pragma unroll
    for (int k = 0; k < NW; k++) t += sred[k];
    return t;
}

template <int NW>
__device__ __forceinline__ float block_max(float v) {
    __shared__ float sred[8];
    __syncthreads();
#pragma unroll
    for (int o = 16; o; o >>= 1) v = fmaxf(v, __shfl_xor_sync(0xffffffffu, v, o));
    if ((threadIdx.x & 31) == 0) sred[threadIdx.x >> 5] = v;
    __syncthreads();
    float t = -3.4e38f;
#pragma unroll
    for (int k = 0; k < NW; k++) t = fmaxf(t, sred[k]);
    return t;
}

// ---------------- K1: split-K partials of P = X^T @ W1 (per head) ----------------
// head 0: it  -> X = xt ; head 1: inw -> X = xn ; head 2: t2n -> X = xn ; head 3: n2t -> X = xt
__global__ __launch_bounds__(256) void k_part1(
    const float* __restrict__ xt, const float* __restrict__ xn,
    const float* __restrict__ w_it, const float* __restrict__ w_inw,
    const float* __restrict__ w_t2n, const float* __restrict__ w_n2t)
{
    int head = blockIdx.z;
    const float* A = (head == 0 || head == 3) ? xt : xn;
    const float* B = (head == 0) ? w_it : (head == 1) ? w_inw : (head == 2) ? w_t2n : w_n2t;
    int mt = blockIdx.x & 1, nt = blockIdx.x >> 1;
    int chunk = blockIdx.y;
    float acc[4][4] = {};
    gemm_tn_tile(A, B, 128, chunk * CHK, chunk * CHK + CHK, mt * 64, nt * 64, acc);
    float* C = g_part1 + (size_t)(head * NCH + chunk) * 16384;
    int tx = threadIdx.x & 15, ty = threadIdx.x >> 4;
    int r0 = mt * 64 + ty * 4, c0 = nt * 64 + tx * 4;
#pragma unroll
    for (int u = 0; u < 4; u++)
#pragma unroll
        for (int v = 0; v < 4; v++)
            C[(r0 + u) * 128 + c0 + v] = acc[u][v];
}

// ---------------- K2: reduce partials + bias + relu ----------------
__global__ __launch_bounds__(256) void k_red1(
    const float* __restrict__ b_it, const float* __restrict__ b_inw,
    const float* __restrict__ b_t2n, const float* __restrict__ b_n2t)
{
    int head = blockIdx.y;
    int i = blockIdx.x * 256 + threadIdx.x;   // < 16384
    const float* b = (head == 0) ? b_it : (head == 1) ? b_inw : (head == 2) ? b_t2n : b_n2t;
    float s = b[i & 127];
#pragma unroll
    for (int c = 0; c < NCH; c++)
        s += g_part1[(size_t)(head * NCH + c) * 16384 + i];
    g_P1[head * 16384 + i] = fmaxf(s, 0.f);
}

// ---------------- K3: M = P1 @ W2 + b2 ----------------
__global__ __launch_bounds__(256) void k_M(
    const float* __restrict__ w2_it, const float* __restrict__ w2_inw,
    const float* __restrict__ w2_t2n, const float* __restrict__ w2_n2t,
    const float* __restrict__ b2_it, const float* __restrict__ b2_inw,
    const float* __restrict__ b2_t2n, const float* __restrict__ b2_n2t)
{
    int head = blockIdx.z;
    const float* B = (head == 0) ? w2_it : (head == 1) ? w2_inw : (head == 2) ? w2_t2n : w2_n2t;
    const float* bias = (head == 0) ? b2_it : (head == 1) ? b2_inw : (head == 2) ? b2_t2n : b2_n2t;
    float acc[4][4] = {};
    gemm_nn_tile(g_P1 + head * 16384, 128, B, 128, 128, blockIdx.x * 64, blockIdx.y * 64, acc);
    float* C = g_M + head * 16384;
    int tx = threadIdx.x & 15, ty = threadIdx.x >> 4;
    int r0 = blockIdx.x * 64 + ty * 4, c0 = blockIdx.y * 64 + tx * 4;
#pragma unroll
    for (int u = 0; u < 4; u++)
#pragma unroll
        for (int v = 0; v < 4; v++)
            C[(r0 + u) * 128 + c0 + v] = acc[u][v] + bias[c0 + v];
}

// ---------------- K4: Hcat[:, head*128 : ] = X_head @ M_head ----------------
// head 0: xt@M_it, head 1: xn@M_inw, head 2: xt@M_t2n, head 3: xn@M_n2t
__global__ __launch_bounds__(256) void k_Hcat(
    const float* __restrict__ xt, const float* __restrict__ xn)
{
    int head = blockIdx.z;
    const float* A = (head == 0 || head == 2) ? xt : xn;
    float acc[4][4] = {};
    gemm_nn_tile(A, 128, g_M + head * 16384, 128, 128, blockIdx.x * 64, blockIdx.y * 64, acc);
    int tx = threadIdx.x & 15, ty = threadIdx.x >> 4;
    int r0 = blockIdx.x * 64 + ty * 4, c0 = head * 128 + blockIdx.y * 64 + tx * 4;
#pragma unroll
    for (int u = 0; u < 4; u++)
#pragma unroll
        for (int v = 0; v < 4; v++)
            g_Hcat[(size_t)(r0 + u) * 512 + c0 + v] = acc[u][v];
}

// ---------------- K5: Htmp = relu(Hcat @ f_W1 + f_b1) ----------------
__global__ __launch_bounds__(256) void k_f1(
    const float* __restrict__ fW1, const float* __restrict__ fb1)
{
    float acc[4][4] = {};
    gemm_nn_tile(g_Hcat, 512, fW1, 128, 512, blockIdx.x * 64, blockIdx.y * 64, acc);
    int tx = threadIdx.x & 15, ty = threadIdx.x >> 4;
    int r0 = blockIdx.x * 64 + ty * 4, c0 = blockIdx.y * 64 + tx * 4;
#pragma unroll
    for (int u = 0; u < 4; u++)
#pragma unroll
        for (int v = 0; v < 4; v++)
            g_Htmp[(r0 + u) * 128 + c0 + v] = fmaxf(acc[u][v] + fb1[c0 + v], 0.f);
}

// ---------------- K6: Hraw = Htmp @ f_W2 + f_b2 ----------------
__global__ __launch_bounds__(256) void k_f2(
    const float* __restrict__ fW2, const float* __restrict__ fb2)
{
    float acc[4][4] = {};
    gemm_nn_tile(g_Htmp, 128, fW2, 128, 128, blockIdx.x * 64, blockIdx.y * 64, acc);
    int tx = threadIdx.x & 15, ty = threadIdx.x >> 4;
    int r0 = blockIdx.x * 64 + ty * 4, c0 = blockIdx.y * 64 + tx * 4;
#pragma unroll
    for (int u = 0; u < 4; u++)
#pragma unroll
        for (int v = 0; v < 4; v++)
            g_Hraw[(r0 + u) * 128 + c0 + v] = acc[u][v] + fb2[c0 + v];
}

// ---------------- K7: per-column standardize + softmax; write H and logH ----------------
__global__ __launch_bounds__(256) void k_colsm()
{
    int e = blockIdx.x;
    __shared__ float s[NTOT];
    int tid = threadIdx.x;
    for (int n = tid; n < NTOT; n += 256) s[n] = g_Hraw[n * 128 + e];
    __syncthreads();

    float lsum = 0.f;
    for (int n = tid; n < NTOT; n += 256) lsum += s[n];
    float mean = block_sum<8>(lsum) * (1.f / NTOT);

    float lss = 0.f;
    for (int n = tid; n < NTOT; n += 256) { float d = s[n] - mean; lss += d * d; }
    float var = block_sum<8>(lss) * (1.f / (NTOT - 1));
    float inv = 1.f / (sqrtf(var) + EPSV);

    float lmax = -3.4e38f;
    for (int n = tid; n < NTOT; n += 256) {
        float z = (s[n] - mean) * inv;
        s[n] = z;
        lmax = fmaxf(lmax, z);
    }
    __syncthreads();          // everyone done writing z
    float mx = block_max<8>(lmax);

    float lse = 0.f;
    for (int n = tid; n < NTOT; n += 256) lse += __expf(s[n] - mx);
    float sum = block_sum<8>(lse);
    float invs = 1.f / sum;
    float lls = __logf(sum);

    for (int n = tid; n < NTOT; n += 256) {
        float z = s[n];
        g_H[n * 128 + e]    = __expf(z - mx) * invs;
        g_logH[n * 128 + e] = (z - mx) - lls;
    }
}

// ---------------- K8: pairwise JSD -> per-column partial sums ----------------
// grid.x: 36 upper-triangle 16x16 tiles; grid.y: 8 chunks of 256 nodes
__global__ __launch_bounds__(256) void k_jsd()
{
    int t = blockIdx.x;
    int bi = 0, rem = t;
    while (rem >= 8 - bi) { rem -= 8 - bi; bi++; }
    int bj = bi + rem;
    int tid = threadIdx.x;
    int ti = tid & 15, tj = tid >> 4;
    int i = bi * 16 + ti, j = bj * 16 + tj;

    __shared__ float sHi[16][16], sLi[16][16], sHj[16][16], sLj[16][16];
    float acci = 0.f, accj = 0.f;
    int lr = tid >> 4, lc = tid & 15;
    int nBeg = blockIdx.y * 256;

    for (int n0 = nBeg; n0 < nBeg + 256; n0 += 16) {
        __syncthreads();
        int n = n0 + lr;
        sHi[lr][lc] = g_H   [n * 128 + bi * 16 + lc];
        sLi[lr][lc] = g_logH[n * 128 + bi * 16 + lc];
        sHj[lr][lc] = g_H   [n * 128 + bj * 16 + lc];
        sLj[lr][lc] = g_logH[n * 128 + bj * 16 + lc];
        __syncthreads();
#pragma unroll
        for (int r = 0; r < 16; r++) {
            float hi = sHi[r][ti], hj = sHj[r][tj];
            float m  = 0.5f * (hi + hj);
            float lm = __logf(m);
            acci += hi * (sLi[r][ti] - lm);
            accj += hj * (sLj[r][tj] - lm);
        }
    }
    float v = (i < j) ? 0.5f * (acci + accj) : 0.f;

    __shared__ float red[16][16];
    __syncthreads();
    red[tj][ti] = v;
    __syncthreads();

    float* out = g_jpart + (size_t)(blockIdx.y * 36 + blockIdx.x) * 128;
    if (tid < 128) out[tid] = 0.f;
    __syncthreads();
    if (tid < 16) {
        float si = 0.f, sj = 0.f;
#pragma unroll
        for (int r = 0; r < 16; r++) { si += red[r][tid]; sj += red[tid][r]; }
        out[bi * 16 + tid] += si;     // column-i contributions
        out[bj * 16 + tid] += sj;     // column-j contributions (same thread handles overlap)
    }
}

// ---------------- K9: jm -> standardized -> softmax -> w ----------------
__global__ __launch_bounds__(128) void k_w()
{
    int e = threadIdx.x;
    float cs = 0.f;
    for (int r = 0; r < JROWS; r++) cs += g_jpart[r * 128 + e];
    float jm = cs * (1.f / 128.f);

    float mean = block_sum<4>(jm) * (1.f / 128.f);
    float d = jm - mean;
    float var = block_sum<4>(d * d) * (1.f / 127.f);
    float njm = d / (sqrtf(var) + EPSV);

    float mx = block_max<4>(njm);
    float ex = __expf(njm - mx);
    float sum = block_sum<4>(ex);
    g_w[e] = ex / sum;
}

// ---------------- K10: Y = x @ theta (both sides) ----------------
__global__ __launch_bounds__(256) void k_Y(
    const float* __restrict__ xt, const float* __restrict__ xn,
    const float* __restrict__ th_t, const float* __restrict__ th_n)
{
    int side = blockIdx.z;
    const float* A = side ? xn : xt;
    const float* B = side ? th_n : th_t;
    float acc[4][4] = {};
    gemm_nn_tile(A, 128, B, 128, 128, blockIdx.x * 64, blockIdx.y * 64, acc);
    float* C = g_Y + (size_t)side * NTOT * 128;
    int tx = threadIdx.x & 15, ty = threadIdx.x >> 4;
    int r0 = blockIdx.x * 64 + ty * 4, c0 = blockIdx.y * 64 + tx * 4;
#pragma unroll
    for (int u = 0; u < 4; u++)
#pragma unroll
        for (int v = 0; v < 4; v++)
            C[(r0 + u) * 128 + c0 + v] = acc[u][v];
}

// ---------------- K11: split-K partials of Z = H^T @ Y ----------------
__global__ __launch_bounds__(256) void k_partZ()
{
    int side = blockIdx.z;
    int mt = blockIdx.x & 1, nt = blockIdx.x >> 1;
    int chunk = blockIdx.y;
    float acc[4][4] = {};
    gemm_tn_tile(g_H, g_Y + (size_t)side * NTOT * 128, 128,
                 chunk * CHK, chunk * CHK + CHK, mt * 64, nt * 64, acc);
    float* C = g_partZ + (size_t)(side * NCH + chunk) * 16384;
    int tx = threadIdx.x & 15, ty = threadIdx.x >> 4;
    int r0 = mt * 64 + ty * 4, c0 = nt * 64 + tx * 4;
#pragma unroll
    for (int u = 0; u < 4; u++)
#pragma unroll
        for (int v = 0; v < 4; v++)
            C[(r0 + u) * 128 + c0 + v] = acc[u][v];
}

// ---------------- K12: Zw[e,d] = w[e] * sum_c partZ ----------------
__global__ __launch_bounds__(256) void k_redZ()
{
    int side = blockIdx.y;
    int i = blockIdx.x * 256 + threadIdx.x;   // < 16384
    float s = 0.f;
#pragma unroll
    for (int c = 0; c < NCH; c++)
        s += g_partZ[(size_t)(side * NCH + c) * 16384 + i];
    g_Zw[side * 16384 + i] = g_w[i >> 7] * s;
}

// ---------------- K13: out = x + elu(H @ Zw) ----------------
__global__ __launch_bounds__(256) void k_final(
    const float* __restrict__ xt, const float* __restrict__ xn,
    float* __restrict__ out)
{
    int side = blockIdx.z;
    const float* x = side ? xn : xt;
    float acc[4][4] = {};
    gemm_nn_tile(g_H, 128, g_Zw + side * 16384, 128, 128, blockIdx.x * 64, blockIdx.y * 64, acc);
    int tx = threadIdx.x & 15, ty = threadIdx.x >> 4;
    int r0 = blockIdx.x * 64 + ty * 4, c0 = blockIdx.y * 64 + tx * 4;
    float* o = out + (size_t)side * NTOT * 128;
#pragma unroll
    for (int u = 0; u < 4; u++)
#pragma unroll
        for (int v = 0; v < 4; v++) {
            float c = acc[u][v];
            float eluv = (c > 0.f) ? c : expm1f(c);
            o[(r0 + u) * 128 + c0 + v] = x[(r0 + u) * 128 + c0 + v] + eluv;
        }
}

// ---------------- launch ----------------
extern "C" void kernel_launch(void* const* d_in, const int* in_sizes, int n_in,
                              void* d_out, int out_size)
{
    const float* xt    = (const float*)d_in[0];
    const float* xn    = (const float*)d_in[1];
    const float* itW1  = (const float*)d_in[2];
    const float* itb1  = (const float*)d_in[3];
    const float* itW2  = (const float*)d_in[4];
    const float* itb2  = (const float*)d_in[5];
    const float* inwW1 = (const float*)d_in[6];
    const float* inwb1 = (const float*)d_in[7];
    const float* inwW2 = (const float*)d_in[8];
    const float* inwb2 = (const float*)d_in[9];
    const float* t2nW1 = (const float*)d_in[10];
    const float* t2nb1 = (const float*)d_in[11];
    const float* t2nW2 = (const float*)d_in[12];
    const float* t2nb2 = (const float*)d_in[13];
    const float* n2tW1 = (const float*)d_in[14];
    const float* n2tb1 = (const float*)d_in[15];
    const float* n2tW2 = (const float*)d_in[16];
    const float* n2tb2 = (const float*)d_in[17];
    const float* fW1   = (const float*)d_in[18];
    const float* fb1   = (const float*)d_in[19];
    const float* fW2   = (const float*)d_in[20];
    const float* fb2   = (const float*)d_in[21];
    const float* thT   = (const float*)d_in[22];
    const float* thN   = (const float*)d_in[23];
    float* out = (float*)d_out;

    k_part1<<<dim3(4, NCH, 4), 256>>>(xt, xn, itW1, inwW1, t2nW1, n2tW1);
    k_red1 <<<dim3(64, 4), 256>>>(itb1, inwb1, t2nb1, n2tb1);
    k_M    <<<dim3(2, 2, 4), 256>>>(itW2, inwW2, t2nW2, n2tW2, itb2, inwb2, t2nb2, n2tb2);
    k_Hcat <<<dim3(32, 2, 4), 256>>>(xt, xn);
    k_f1   <<<dim3(32, 2), 256>>>(fW1, fb1);
    k_f2   <<<dim3(32, 2), 256>>>(fW2, fb2);
    k_colsm<<<128, 256>>>();
    k_jsd  <<<dim3(36, 8), 256>>>();
    k_w    <<<1, 128>>>();
    k_Y    <<<dim3(32, 2, 2), 256>>>(xt, xn, thT, thN);
    k_partZ<<<dim3(4, NCH, 2), 256>>>();
    k_redZ <<<dim3(64, 2), 256>>>();
    k_final<<<dim3(32, 2, 2), 256>>>(xt, xn, out);
}

// round 5
// speedup vs baseline: 1.1374x; 1.1374x over previous
#include <cuda_runtime.h>

// ---------------- problem constants ----------------
#define NTOT 2048      // N*T
#define JROWS 288      // 36 tiles * 8 n-chunks
#define EPSV 1e-6f

typedef unsigned long long u64;

// ---------------- scratch (device globals; no allocation) ----------------
static __device__ __align__(16) float g_part1[1048576];       // part1 partials, reused for f1 partials
static __device__ __align__(16) float g_P1  [4 * 128 * 128];
static __device__ __align__(16) float g_M   [4 * 128 * 128];
static __device__ __align__(16) float g_Hcat[NTOT * 512];
static __device__ __align__(16) float g_Htmp[NTOT * 128];
static __device__ __align__(16) float g_Hraw[NTOT * 128];
static __device__ __align__(16) float g_H   [NTOT * 128];
static __device__ __align__(16) float g_logH[NTOT * 128];
static __device__ __align__(16) float g_jpart[JROWS * 128];
static __device__ __align__(16) float g_w   [128];
static __device__ __align__(16) float g_Y   [2 * NTOT * 128];
static __device__ __align__(16) float g_partZ[2 * 32 * 128 * 128];
static __device__ __align__(16) float g_Zw  [2 * 128 * 128];

// ---------------- f32x2 helpers ----------------
__device__ __forceinline__ u64 pack_dup(float x) {
    u64 r; asm("mov.b64 %0, {%1, %1};" : "=l"(r) : "f"(x)); return r;
}
__device__ __forceinline__ void ffma2(u64& d, u64 a, u64 b) {
    asm("fma.rn.f32x2 %0, %1, %2, %0;" : "+l"(d) : "l"(a), "l"(b));
}
__device__ __forceinline__ float4 accrow(u64 a, u64 b) {
    float4 r;
    asm("mov.b64 {%0, %1}, %4;\n\tmov.b64 {%2, %3}, %5;"
        : "=f"(r.x), "=f"(r.y), "=f"(r.z), "=f"(r.w) : "l"(a), "l"(b));
    return r;
}

// ---------------- tile loaders (256 threads, BK=16, BN=128) ----------------
// B tile: 16 x 128 from row-major B (ldb floats), rows kRow..kRow+15
__device__ __forceinline__ void ldgB(const float* __restrict__ B, int ldb, int kRow,
                                     int tid, float4& r0, float4& r1) {
    int i0 = tid * 2, i1 = i0 + 1;
    r0 = *(const float4*)(B + (size_t)(kRow + (i0 >> 5)) * ldb + (i0 & 31) * 4);
    r1 = *(const float4*)(B + (size_t)(kRow + (i1 >> 5)) * ldb + (i1 & 31) * 4);
}
__device__ __forceinline__ void stsB(float* sB, int tid, float4 r0, float4 r1) {
    int i0 = tid * 2, i1 = i0 + 1;
    *(float4*)(sB + (i0 >> 5) * 128 + (i0 & 31) * 4) = r0;
    *(float4*)(sB + (i1 >> 5) * 128 + (i1 & 31) * 4) = r1;
}
// A tile for NN (A row-major [M x lda]); BM=64: sA transposed [16][68]
__device__ __forceinline__ float4 ldgA64(const float* __restrict__ A, int lda,
                                         int rowBase, int k0, int tid) {
    return *(const float4*)(A + (size_t)(rowBase + (tid >> 2)) * lda + k0 + (tid & 3) * 4);
}
__device__ __forceinline__ void stsA64(float* sA, int tid, float4 v) {
    int r = tid >> 2, kc = (tid & 3) * 4;
    sA[(kc + 0) * 68 + r] = v.x;
    sA[(kc + 1) * 68 + r] = v.y;
    sA[(kc + 2) * 68 + r] = v.z;
    sA[(kc + 3) * 68 + r] = v.w;
}
// A tile for TN (A K-major [K x 128]); direct copy into sA [16][68]
__device__ __forceinline__ float4 ldgAt(const float* __restrict__ A, int mBase,
                                        int k0, int tid) {
    return *(const float4*)(A + (size_t)(k0 + (tid >> 4)) * 128 + mBase + (tid & 15) * 4);
}
__device__ __forceinline__ void stsAt(float* sA, int tid, float4 v) {
    *(float4*)(sA + (tid >> 4) * 68 + (tid & 15) * 4) = v;
}
// A tile for NN BM=32: sA transposed [16][36]; only tids < 128 participate
__device__ __forceinline__ float4 ldgA32(const float* __restrict__ A, int lda,
                                         int rowBase, int k0, int tid) {
    return *(const float4*)(A + (size_t)(rowBase + (tid >> 2)) * lda + k0 + (tid & 3) * 4);
}
__device__ __forceinline__ void stsA32(float* sA, int tid, float4 v) {
    int r = tid >> 2, kc = (tid & 3) * 4;
    sA[(kc + 0) * 36 + r] = v.x;
    sA[(kc + 1) * 36 + r] = v.y;
    sA[(kc + 2) * 36 + r] = v.z;
    sA[(kc + 3) * 36 + r] = v.w;
}

// ---------------- compute blocks ----------------
__device__ __forceinline__ void comp64(const float* sA, const float* sB,
                                       u64 (&acc)[4][4], int tx, int ty) {
#pragma unroll
    for (int k = 0; k < 16; k++) {
        float4 a4 = *(const float4*)(sA + k * 68 + ty * 4);
        ulonglong2 b0 = *(const ulonglong2*)(sB + k * 128 + tx * 4);
        ulonglong2 b1 = *(const ulonglong2*)(sB + k * 128 + 64 + tx * 4);
        u64 d0 = pack_dup(a4.x), d1 = pack_dup(a4.y), d2 = pack_dup(a4.z), d3 = pack_dup(a4.w);
        ffma2(acc[0][0], d0, b0.x); ffma2(acc[0][1], d0, b0.y);
        ffma2(acc[0][2], d0, b1.x); ffma2(acc[0][3], d0, b1.y);
        ffma2(acc[1][0], d1, b0.x); ffma2(acc[1][1], d1, b0.y);
        ffma2(acc[1][2], d1, b1.x); ffma2(acc[1][3], d1, b1.y);
        ffma2(acc[2][0], d2, b0.x); ffma2(acc[2][1], d2, b0.y);
        ffma2(acc[2][2], d2, b1.x); ffma2(acc[2][3], d2, b1.y);
        ffma2(acc[3][0], d3, b0.x); ffma2(acc[3][1], d3, b0.y);
        ffma2(acc[3][2], d3, b1.x); ffma2(acc[3][3], d3, b1.y);
    }
}
__device__ __forceinline__ void comp32(const float* sA, const float* sB,
                                       u64 (&acc)[2][4], int tx, int ty) {
#pragma unroll
    for (int k = 0; k < 16; k++) {
        float2 a2 = *(const float2*)(sA + k * 36 + ty * 2);
        ulonglong2 b0 = *(const ulonglong2*)(sB + k * 128 + tx * 4);
        ulonglong2 b1 = *(const ulonglong2*)(sB + k * 128 + 64 + tx * 4);
        u64 d0 = pack_dup(a2.x), d1 = pack_dup(a2.y);
        ffma2(acc[0][0], d0, b0.x); ffma2(acc[0][1], d0, b0.y);
        ffma2(acc[0][2], d0, b1.x); ffma2(acc[0][3], d0, b1.y);
        ffma2(acc[1][0], d1, b0.x); ffma2(acc[1][1], d1, b0.y);
        ffma2(acc[1][2], d1, b1.x); ffma2(acc[1][3], d1, b1.y);
    }
}

// ---------------- block reductions ----------------
template <int NW>
__device__ __forceinline__ float block_sum(float v) {
    __shared__ float sred[8];
    __syncthreads();
#pragma unroll
    for (int o = 16; o; o >>= 1) v += __shfl_xor_sync(0xffffffffu, v, o);
    if ((threadIdx.x & 31) == 0) sred[threadIdx.x >> 5] = v;
    __syncthreads();
    float t = 0.f;
#pragma unroll
    for (int k = 0; k < NW; k++) t += sred[k];
    return t;
}
template <int NW>
__device__ __forceinline__ float block_max(float v) {
    __shared__ float sred[8];
    __syncthreads();
#pragma unroll
    for (int o = 16; o; o >>= 1) v = fmaxf(v, __shfl_xor_sync(0xffffffffu, v, o));
    if ((threadIdx.x & 31) == 0) sred[threadIdx.x >> 5] = v;
    __syncthreads();
    float t = -3.4e38f;
#pragma unroll
    for (int k = 0; k < NW; k++) t = fmaxf(t, sred[k]);
    return t;
}

// ================= K1: split-K partials of P = X^T @ W1 (per head) =================
// grid (2 m-tiles, 16 chunks, 4 heads); K-chunk = 128
__global__ __launch_bounds__(256) void k_part1(
    const float* __restrict__ xt, const float* __restrict__ xn,
    const float* __restrict__ w_it, const float* __restrict__ w_inw,
    const float* __restrict__ w_t2n, const float* __restrict__ w_n2t)
{
    __shared__ __align__(16) float sA[16 * 68];
    __shared__ __align__(16) float sB[16 * 128];
    int head = blockIdx.z;
    const float* A = (head == 0 || head == 3) ? xt : xn;
    const float* B = (head == 0) ? w_it : (head == 1) ? w_inw : (head == 2) ? w_t2n : w_n2t;
    int mBase = blockIdx.x * 64;
    int kBeg = blockIdx.y * 128;
    int tid = threadIdx.x, tx = tid & 15, ty = tid >> 4;
    u64 acc[4][4] = {};
    float4 ra = ldgAt(A, mBase, kBeg, tid);
    float4 rb0, rb1; ldgB(B, 128, kBeg, tid, rb0, rb1);
    for (int s = 0; s < 8; s++) {
        __syncthreads();
        stsAt(sA, tid, ra); stsB(sB, tid, rb0, rb1);
        __syncthreads();
        if (s < 7) { ra = ldgAt(A, mBase, kBeg + (s + 1) * 16, tid); ldgB(B, 128, kBeg + (s + 1) * 16, tid, rb0, rb1); }
        comp64(sA, sB, acc, tx, ty);
    }
    float* C = g_part1 + (size_t)(head * 16 + blockIdx.y) * 16384;
    int r0 = mBase + ty * 4;
#pragma unroll
    for (int u = 0; u < 4; u++) {
        *(float4*)(C + (r0 + u) * 128 + tx * 4)      = accrow(acc[u][0], acc[u][1]);
        *(float4*)(C + (r0 + u) * 128 + 64 + tx * 4) = accrow(acc[u][2], acc[u][3]);
    }
}

// ================= K2: reduce 16 chunks + bias + relu -> P1 =================
__global__ __launch_bounds__(256) void k_red1(
    const float* __restrict__ b_it, const float* __restrict__ b_inw,
    const float* __restrict__ b_t2n, const float* __restrict__ b_n2t)
{
    int head = blockIdx.y;
    int i4 = blockIdx.x * 256 + threadIdx.x;   // < 4096 float4s per head
    const float* b = (head == 0) ? b_it : (head == 1) ? b_inw : (head == 2) ? b_t2n : b_n2t;
    float4 s = ((const float4*)b)[i4 & 31];
#pragma unroll
    for (int c = 0; c < 16; c++) {
        float4 p = ((const float4*)g_part1)[(size_t)(head * 16 + c) * 4096 + i4];
        s.x += p.x; s.y += p.y; s.z += p.z; s.w += p.w;
    }
    s.x = fmaxf(s.x, 0.f); s.y = fmaxf(s.y, 0.f); s.z = fmaxf(s.z, 0.f); s.w = fmaxf(s.w, 0.f);
    ((float4*)g_P1)[head * 4096 + i4] = s;
}

// ================= K3: M = P1 @ W2 + b2 (BM=32) =================
// grid (4 m-tiles, 1, 4 heads)
__global__ __launch_bounds__(256) void k_M(
    const float* __restrict__ w2_it, const float* __restrict__ w2_inw,
    const float* __restrict__ w2_t2n, const float* __restrict__ w2_n2t,
    const float* __restrict__ b2_it, const float* __restrict__ b2_inw,
    const float* __restrict__ b2_t2n, const float* __restrict__ b2_n2t)
{
    __shared__ __align__(16) float sA[16 * 36];
    __shared__ __align__(16) float sB[16 * 128];
    int head = blockIdx.z;
    const float* A = g_P1 + head * 16384;
    const float* B = (head == 0) ? w2_it : (head == 1) ? w2_inw : (head == 2) ? w2_t2n : w2_n2t;
    const float* bias = (head == 0) ? b2_it : (head == 1) ? b2_inw : (head == 2) ? b2_t2n : b2_n2t;
    int rowBase = blockIdx.x * 32;
    int tid = threadIdx.x, tx = tid & 15, ty = tid >> 4;
    u64 acc[2][4] = {};
    float4 ra; if (tid < 128) ra = ldgA32(A, 128, rowBase, 0, tid);
    float4 rb0, rb1; ldgB(B, 128, 0, tid, rb0, rb1);
    for (int s = 0; s < 8; s++) {
        __syncthreads();
        if (tid < 128) stsA32(sA, tid, ra);
        stsB(sB, tid, rb0, rb1);
        __syncthreads();
        if (s < 7) { if (tid < 128) ra = ldgA32(A, 128, rowBase, (s + 1) * 16, tid); ldgB(B, 128, (s + 1) * 16, tid, rb0, rb1); }
        comp32(sA, sB, acc, tx, ty);
    }
    float* C = g_M + head * 16384;
    float4 bb0 = *(const float4*)(bias + tx * 4);
    float4 bb1 = *(const float4*)(bias + 64 + tx * 4);
    int r0 = rowBase + ty * 2;
#pragma unroll
    for (int u = 0; u < 2; u++) {
        float4 v0 = accrow(acc[u][0], acc[u][1]);
        float4 v1 = accrow(acc[u][2], acc[u][3]);
        v0.x += bb0.x; v0.y += bb0.y; v0.z += bb0.z; v0.w += bb0.w;
        v1.x += bb1.x; v1.y += bb1.y; v1.z += bb1.z; v1.w += bb1.w;
        *(float4*)(C + (r0 + u) * 128 + tx * 4) = v0;
        *(float4*)(C + (r0 + u) * 128 + 64 + tx * 4) = v1;
    }
}

// ================= K4: Hcat[:, head*128:] = X_head @ M_head (BM=64) =================
// grid (32 m-tiles, 1, 4 heads)
__global__ __launch_bounds__(256) void k_Hcat(
    const float* __restrict__ xt, const float* __restrict__ xn)
{
    __shared__ __align__(16) float sA[16 * 68];
    __shared__ __align__(16) float sB[16 * 128];
    int head = blockIdx.z;
    const float* A = (head == 0 || head == 2) ? xt : xn;
    const float* B = g_M + head * 16384;
    int rowBase = blockIdx.x * 64;
    int tid = threadIdx.x, tx = tid & 15, ty = tid >> 4;
    u64 acc[4][4] = {};
    float4 ra = ldgA64(A, 128, rowBase, 0, tid);
    float4 rb0, rb1; ldgB(B, 128, 0, tid, rb0, rb1);
    for (int s = 0; s < 8; s++) {
        __syncthreads();
        stsA64(sA, tid, ra); stsB(sB, tid, rb0, rb1);
        __syncthreads();
        if (s < 7) { ra = ldgA64(A, 128, rowBase, (s + 1) * 16, tid); ldgB(B, 128, (s + 1) * 16, tid, rb0, rb1); }
        comp64(sA, sB, acc, tx, ty);
    }
    int r0 = rowBase + ty * 4;
    int c0 = head * 128;
#pragma unroll
    for (int u = 0; u < 4; u++) {
        *(float4*)(g_Hcat + (size_t)(r0 + u) * 512 + c0 + tx * 4)      = accrow(acc[u][0], acc[u][1]);
        *(float4*)(g_Hcat + (size_t)(r0 + u) * 512 + c0 + 64 + tx * 4) = accrow(acc[u][2], acc[u][3]);
    }
}

// ================= K5: split-K partials of Hcat @ f_W1 (BM=64) =================
// grid (32 m-tiles, 4 chunks); K-chunk = 128
__global__ __launch_bounds__(256) void k_f1(const float* __restrict__ fW1)
{
    __shared__ __align__(16) float sA[16 * 68];
    __shared__ __align__(16) float sB[16 * 128];
    int rowBase = blockIdx.x * 64;
    int kBeg = blockIdx.y * 128;
    int tid = threadIdx.x, tx = tid & 15, ty = tid >> 4;
    u64 acc[4][4] = {};
    float4 ra = ldgA64(g_Hcat, 512, rowBase, kBeg, tid);
    float4 rb0, rb1; ldgB(fW1, 128, kBeg, tid, rb0, rb1);
    for (int s = 0; s < 8; s++) {
        __syncthreads();
        stsA64(sA, tid, ra); stsB(sB, tid, rb0, rb1);
        __syncthreads();
        if (s < 7) { ra = ldgA64(g_Hcat, 512, rowBase, kBeg + (s + 1) * 16, tid); ldgB(fW1, 128, kBeg + (s + 1) * 16, tid, rb0, rb1); }
        comp64(sA, sB, acc, tx, ty);
    }
    float* C = g_part1 + (size_t)blockIdx.y * 262144;
    int r0 = rowBase + ty * 4;
#pragma unroll
    for (int u = 0; u < 4; u++) {
        *(float4*)(C + (size_t)(r0 + u) * 128 + tx * 4)      = accrow(acc[u][0], acc[u][1]);
        *(float4*)(C + (size_t)(r0 + u) * 128 + 64 + tx * 4) = accrow(acc[u][2], acc[u][3]);
    }
}

// ================= K6: reduce 4 chunks + bias + relu -> Htmp =================
__global__ __launch_bounds__(256) void k_f1red(const float* __restrict__ fb1)
{
    int i4 = blockIdx.x * 256 + threadIdx.x;   // < 65536
    float4 s = ((const float4*)fb1)[i4 & 31];
#pragma unroll
    for (int c = 0; c < 4; c++) {
        float4 p = ((const float4*)g_part1)[(size_t)c * 65536 + i4];
        s.x += p.x; s.y += p.y; s.z += p.z; s.w += p.w;
    }
    s.x = fmaxf(s.x, 0.f); s.y = fmaxf(s.y, 0.f); s.z = fmaxf(s.z, 0.f); s.w = fmaxf(s.w, 0.f);
    ((float4*)g_Htmp)[i4] = s;
}

// ================= K7: Hraw = Htmp @ f_W2 + f_b2 (BM=32) =================
// grid (64)
__global__ __launch_bounds__(256) void k_f2(
    const float* __restrict__ fW2, const float* __restrict__ fb2)
{
    __shared__ __align__(16) float sA[16 * 36];
    __shared__ __align__(16) float sB[16 * 128];
    int rowBase = blockIdx.x * 32;
    int tid = threadIdx.x, tx = tid & 15, ty = tid >> 4;
    u64 acc[2][4] = {};
    float4 ra; if (tid < 128) ra = ldgA32(g_Htmp, 128, rowBase, 0, tid);
    float4 rb0, rb1; ldgB(fW2, 128, 0, tid, rb0, rb1);
    for (int s = 0; s < 8; s++) {
        __syncthreads();
        if (tid < 128) stsA32(sA, tid, ra);
        stsB(sB, tid, rb0, rb1);
        __syncthreads();
        if (s < 7) { if (tid < 128) ra = ldgA32(g_Htmp, 128, rowBase, (s + 1) * 16, tid); ldgB(fW2, 128, (s + 1) * 16, tid, rb0, rb1); }
        comp32(sA, sB, acc, tx, ty);
    }
    float4 bb0 = *(const float4*)(fb2 + tx * 4);
    float4 bb1 = *(const float4*)(fb2 + 64 + tx * 4);
    int r0 = rowBase + ty * 2;
#pragma unroll
    for (int u = 0; u < 2; u++) {
        float4 v0 = accrow(acc[u][0], acc[u][1]);
        float4 v1 = accrow(acc[u][2], acc[u][3]);
        v0.x += bb0.x; v0.y += bb0.y; v0.z += bb0.z; v0.w += bb0.w;
        v1.x += bb1.x; v1.y += bb1.y; v1.z += bb1.z; v1.w += bb1.w;
        *(float4*)(g_Hraw + (size_t)(r0 + u) * 128 + tx * 4) = v0;
        *(float4*)(g_Hraw + (size_t)(r0 + u) * 128 + 64 + tx * 4) = v1;
    }
}

// ================= K8: per-column standardize + softmax -> H, logH =================
__global__ __launch_bounds__(256) void k_colsm()
{
    int e = blockIdx.x;
    __shared__ float s[NTOT];
    int tid = threadIdx.x;
    for (int n = tid; n < NTOT; n += 256) s[n] = g_Hraw[n * 128 + e];
    __syncthreads();

    float lsum = 0.f;
    for (int n = tid; n < NTOT; n += 256) lsum += s[n];
    float mean = block_sum<8>(lsum) * (1.f / NTOT);

    float lss = 0.f;
    for (int n = tid; n < NTOT; n += 256) { float d = s[n] - mean; lss += d * d; }
    float var = block_sum<8>(lss) * (1.f / (NTOT - 1));
    float inv = 1.f / (sqrtf(var) + EPSV);

    float lmax = -3.4e38f;
    for (int n = tid; n < NTOT; n += 256) {
        float z = (s[n] - mean) * inv;
        s[n] = z;
        lmax = fmaxf(lmax, z);
    }
    __syncthreads();
    float mx = block_max<8>(lmax);

    float lse = 0.f;
    for (int n = tid; n < NTOT; n += 256) lse += __expf(s[n] - mx);
    float sum = block_sum<8>(lse);
    float invs = 1.f / sum;
    float lls = __logf(sum);

    for (int n = tid; n < NTOT; n += 256) {
        float z = s[n];
        g_H[n * 128 + e]    = __expf(z - mx) * invs;
        g_logH[n * 128 + e] = (z - mx) - lls;
    }
}

// ================= K9: pairwise JSD -> per-column partial sums =================
__global__ __launch_bounds__(256) void k_jsd()
{
    int t = blockIdx.x;
    int bi = 0, rem = t;
    while (rem >= 8 - bi) { rem -= 8 - bi; bi++; }
    int bj = bi + rem;
    int tid = threadIdx.x;
    int ti = tid & 15, tj = tid >> 4;
    int i = bi * 16 + ti, j = bj * 16 + tj;

    __shared__ float sHi[16][16], sLi[16][16], sHj[16][16], sLj[16][16];
    float acci = 0.f, accj = 0.f;
    int lr = tid >> 4, lc = tid & 15;
    int nBeg = blockIdx.y * 256;

    for (int n0 = nBeg; n0 < nBeg + 256; n0 += 16) {
        __syncthreads();
        int n = n0 + lr;
        sHi[lr][lc] = g_H   [n * 128 + bi * 16 + lc];
        sLi[lr][lc] = g_logH[n * 128 + bi * 16 + lc];
        sHj[lr][lc] = g_H   [n * 128 + bj * 16 + lc];
        sLj[lr][lc] = g_logH[n * 128 + bj * 16 + lc];
        __syncthreads();
#pragma unroll
        for (int r = 0; r < 16; r++) {
            float hi = sHi[r][ti], hj = sHj[r][tj];
            float m  = 0.5f * (hi + hj);
            float lm = __logf(m);
            acci += hi * (sLi[r][ti] - lm);
            accj += hj * (sLj[r][tj] - lm);
        }
    }
    float v = (i < j) ? 0.5f * (acci + accj) : 0.f;

    __shared__ float red[16][16];
    __syncthreads();
    red[tj][ti] = v;
    __syncthreads();

    float* out = g_jpart + (size_t)(blockIdx.y * 36 + blockIdx.x) * 128;
    if (tid < 128) out[tid] = 0.f;
    __syncthreads();
    if (tid < 16) {
        float si = 0.f, sj = 0.f;
#pragma unroll
        for (int r = 0; r < 16; r++) { si += red[r][tid]; sj += red[tid][r]; }
        out[bi * 16 + tid] += si;
        out[bj * 16 + tid] += sj;
    }
}

// ================= K10: jm -> standardized -> softmax -> w =================
__global__ __launch_bounds__(128) void k_w()
{
    int e = threadIdx.x;
    float cs = 0.f;
    for (int r = 0; r < JROWS; r++) cs += g_jpart[r * 128 + e];
    float jm = cs * (1.f / 128.f);

    float mean = block_sum<4>(jm) * (1.f / 128.f);
    float d = jm - mean;
    float var = block_sum<4>(d * d) * (1.f / 127.f);
    float njm = d / (sqrtf(var) + EPSV);

    float mx = block_max<4>(njm);
    float ex = __expf(njm - mx);
    float sum = block_sum<4>(ex);
    g_w[e] = ex / sum;
}

// ================= K11: Y = x @ theta (BM=32) =================
// grid (64 m-tiles, 1, 2 sides)
__global__ __launch_bounds__(256) void k_Y(
    const float* __restrict__ xt, const float* __restrict__ xn,
    const float* __restrict__ th_t, const float* __restrict__ th_n)
{
    __shared__ __align__(16) float sA[16 * 36];
    __shared__ __align__(16) float sB[16 * 128];
    int side = blockIdx.z;
    const float* A = side ? xn : xt;
    const float* B = side ? th_n : th_t;
    int rowBase = blockIdx.x * 32;
    int tid = threadIdx.x, tx = tid & 15, ty = tid >> 4;
    u64 acc[2][4] = {};
    float4 ra; if (tid < 128) ra = ldgA32(A, 128, rowBase, 0, tid);
    float4 rb0, rb1; ldgB(B, 128, 0, tid, rb0, rb1);
    for (int s = 0; s < 8; s++) {
        __syncthreads();
        if (tid < 128) stsA32(sA, tid, ra);
        stsB(sB, tid, rb0, rb1);
        __syncthreads();
        if (s < 7) { if (tid < 128) ra = ldgA32(A, 128, rowBase, (s + 1) * 16, tid); ldgB(B, 128, (s + 1) * 16, tid, rb0, rb1); }
        comp32(sA, sB, acc, tx, ty);
    }
    float* C = g_Y + (size_t)side * NTOT * 128;
    int r0 = rowBase + ty * 2;
#pragma unroll
    for (int u = 0; u < 2; u++) {
        *(float4*)(C + (size_t)(r0 + u) * 128 + tx * 4)      = accrow(acc[u][0], acc[u][1]);
        *(float4*)(C + (size_t)(r0 + u) * 128 + 64 + tx * 4) = accrow(acc[u][2], acc[u][3]);
    }
}

// ================= K12: split-K partials of Z = H^T @ Y (BM=64) =================
// grid (2 m-tiles, 32 chunks, 2 sides); K-chunk = 64
__global__ __launch_bounds__(256) void k_partZ()
{
    __shared__ __align__(16) float sA[16 * 68];
    __shared__ __align__(16) float sB[16 * 128];
    int side = blockIdx.z;
    const float* B = g_Y + (size_t)side * NTOT * 128;
    int mBase = blockIdx.x * 64;
    int kBeg = blockIdx.y * 64;
    int tid = threadIdx.x, tx = tid & 15, ty = tid >> 4;
    u64 acc[4][4] = {};
    float4 ra = ldgAt(g_H, mBase, kBeg, tid);
    float4 rb0, rb1; ldgB(B, 128, kBeg, tid, rb0, rb1);
    for (int s = 0; s < 4; s++) {
        __syncthreads();
        stsAt(sA, tid, ra); stsB(sB, tid, rb0, rb1);
        __syncthreads();
        if (s < 3) { ra = ldgAt(g_H, mBase, kBeg + (s + 1) * 16, tid); ldgB(B, 128, kBeg + (s + 1) * 16, tid, rb0, rb1); }
        comp64(sA, sB, acc, tx, ty);
    }
    float* C = g_partZ + (size_t)(side * 32 + blockIdx.y) * 16384;
    int r0 = mBase + ty * 4;
#pragma unroll
    for (int u = 0; u < 4; u++) {
        *(float4*)(C + (r0 + u) * 128 + tx * 4)      = accrow(acc[u][0], acc[u][1]);
        *(float4*)(C + (r0 + u) * 128 + 64 + tx * 4) = accrow(acc[u][2], acc[u][3]);
    }
}

// ================= K13: Zw = w * (sum chunks) =================
__global__ __launch_bounds__(256) void k_redZ()
{
    int side = blockIdx.y;
    int i4 = blockIdx.x * 256 + threadIdx.x;   // < 4096
    float4 s = make_float4(0.f, 0.f, 0.f, 0.f);
#pragma unroll
    for (int c = 0; c < 32; c++) {
        float4 p = ((const float4*)g_partZ)[(size_t)(side * 32 + c) * 4096 + i4];
        s.x += p.x; s.y += p.y; s.z += p.z; s.w += p.w;
    }
    float wv = g_w[i4 >> 5];
    s.x *= wv; s.y *= wv; s.z *= wv; s.w *= wv;
    ((float4*)g_Zw)[side * 4096 + i4] = s;
}

// ================= K14: out = x + elu(H @ Zw) (BM=32) =================
// grid (64 m-tiles, 1, 2 sides)
__global__ __launch_bounds__(256) void k_final(
    const float* __restrict__ xt, const float* __restrict__ xn,
    float* __restrict__ out)
{
    __shared__ __align__(16) float sA[16 * 36];
    __shared__ __align__(16) float sB[16 * 128];
    int side = blockIdx.z;
    const float* x = side ? xn : xt;
    const float* B = g_Zw + side * 16384;
    int rowBase = blockIdx.x * 32;
    int tid = threadIdx.x, tx = tid & 15, ty = tid >> 4;
    u64 acc[2][4] = {};
    float4 ra; if (tid < 128) ra = ldgA32(g_H, 128, rowBase, 0, tid);
    float4 rb0, rb1; ldgB(B, 128, 0, tid, rb0, rb1);
    for (int s = 0; s < 8; s++) {
        __syncthreads();
        if (tid < 128) stsA32(sA, tid, ra);
        stsB(sB, tid, rb0, rb1);
        __syncthreads();
        if (s < 7) { if (tid < 128) ra = ldgA32(g_H, 128, rowBase, (s + 1) * 16, tid); ldgB(B, 128, (s + 1) * 16, tid, rb0, rb1); }
        comp32(sA, sB, acc, tx, ty);
    }
    float* o = out + (size_t)side * NTOT * 128;
    int r0 = rowBase + ty * 2;
#pragma unroll
    for (int u = 0; u < 2; u++) {
#pragma unroll
        for (int h = 0; h < 2; h++) {
            float4 v = accrow(acc[u][h * 2], acc[u][h * 2 + 1]);
            int c = h * 64 + tx * 4;
            float4 xv = *(const float4*)(x + (size_t)(r0 + u) * 128 + c);
            v.x = xv.x + ((v.x > 0.f) ? v.x : expm1f(v.x));
            v.y = xv.y + ((v.y > 0.f) ? v.y : expm1f(v.y));
            v.z = xv.z + ((v.z > 0.f) ? v.z : expm1f(v.z));
            v.w = xv.w + ((v.w > 0.f) ? v.w : expm1f(v.w));
            *(float4*)(o + (size_t)(r0 + u) * 128 + c) = v;
        }
    }
}

// ---------------- launch ----------------
extern "C" void kernel_launch(void* const* d_in, const int* in_sizes, int n_in,
                              void* d_out, int out_size)
{
    const float* xt    = (const float*)d_in[0];
    const float* xn    = (const float*)d_in[1];
    const float* itW1  = (const float*)d_in[2];
    const float* itb1  = (const float*)d_in[3];
    const float* itW2  = (const float*)d_in[4];
    const float* itb2  = (const float*)d_in[5];
    const float* inwW1 = (const float*)d_in[6];
    const float* inwb1 = (const float*)d_in[7];
    const float* inwW2 = (const float*)d_in[8];
    const float* inwb2 = (const float*)d_in[9];
    const float* t2nW1 = (const float*)d_in[10];
    const float* t2nb1 = (const float*)d_in[11];
    const float* t2nW2 = (const float*)d_in[12];
    const float* t2nb2 = (const float*)d_in[13];
    const float* n2tW1 = (const float*)d_in[14];
    const float* n2tb1 = (const float*)d_in[15];
    const float* n2tW2 = (const float*)d_in[16];
    const float* n2tb2 = (const float*)d_in[17];
    const float* fW1   = (const float*)d_in[18];
    const float* fb1   = (const float*)d_in[19];
    const float* fW2   = (const float*)d_in[20];
    const float* fb2   = (const float*)d_in[21];
    const float* thT   = (const float*)d_in[22];
    const float* thN   = (const float*)d_in[23];
    float* out = (float*)d_out;

    k_part1<<<dim3(2, 16, 4), 256>>>(xt, xn, itW1, inwW1, t2nW1, n2tW1);
    k_red1 <<<dim3(16, 4), 256>>>(itb1, inwb1, t2nb1, n2tb1);
    k_M    <<<dim3(4, 1, 4), 256>>>(itW2, inwW2, t2nW2, n2tW2, itb2, inwb2, t2nb2, n2tb2);
    k_Hcat <<<dim3(32, 1, 4), 256>>>(xt, xn);
    k_f1   <<<dim3(32, 4), 256>>>(fW1);
    k_f1red<<<256, 256>>>(fb1);
    k_f2   <<<64, 256>>>(fW2, fb2);
    k_colsm<<<128, 256>>>();
    k_jsd  <<<dim3(36, 8), 256>>>();
    k_w    <<<1, 128>>>();
    k_Y    <<<dim3(64, 1, 2), 256>>>(xt, xn, thT, thN);
    k_partZ<<<dim3(2, 32, 2), 256>>>();
    k_redZ <<<dim3(16, 2), 256>>>();
    k_final<<<dim3(64, 1, 2), 256>>>(xt, xn, out);
}